// round 11
// baseline (speedup 1.0000x reference)
#include <cuda_runtime.h>

#define N_NODES 50000
#define N_EDGES 800000
#define CH 128
#define OUT_CH 64
#define SCAN_B 1024
#define SCAN_NB ((N_NODES + SCAN_B - 1) / SCAN_B)   // 49
#define PAD_A 36
#define PAD_B 136
#define GEMM_SMEM ((128 * PAD_B + 128 * PAD_A) * 4)

// ---- persistent device scratch (no allocation allowed) ----
__device__ int   g_is64;
__device__ int   g_deg[N_NODES];
__device__ float g_dinv[N_NODES];
__device__ int   g_rowptr[N_NODES + 1];
__device__ int   g_fill[N_NODES];
__device__ int   g_bsum[64];
__device__ int   g_src[N_EDGES];
__device__ int   g_dst[N_EDGES];
__device__ int   g_csr[N_EDGES];
__device__ __align__(16) float g_h1[(size_t)N_NODES * CH];
__device__ __align__(16) float g_hidden[(size_t)N_NODES * CH];
__device__ __align__(16) float g_h23[(size_t)N_NODES * CH];
__device__ __align__(16) float g_wc[CH * CH];

// ---------------------------------------------------------------------------
// init deg/fill, pack [W2|W3], detect edge dtype
__global__ void k_pre(const void* ei, const float* __restrict__ W2,
                      const float* __restrict__ W3) {
    int i = blockIdx.x * blockDim.x + threadIdx.x;
    if (i < N_NODES) { g_deg[i] = 0; g_fill[i] = 0; }
    if (i < CH * CH) {
        int k = i >> 7, c = i & 127;
        g_wc[i] = (c < OUT_CH) ? W2[k * OUT_CH + c] : W3[k * OUT_CH + (c - OUT_CH)];
    }
    if (i == 0) {
        const long long* p = (const long long*)ei;
        int ok64 = 1;
        for (int t = 0; t < 256; t++) {
            long long v = p[t];
            if (v < 0 || v >= N_NODES) { ok64 = 0; break; }
        }
        g_is64 = ok64;
    }
}

// fused: convert edges to int32, accumulate target degrees
__global__ void k_deg(const void* __restrict__ ei) {
    int e = blockIdx.x * blockDim.x + threadIdx.x;
    if (e >= N_EDGES) return;
    int s, c;
    if (g_is64) {
        s = (int)(((const long long*)ei)[e]);
        c = (int)(((const long long*)ei)[N_EDGES + e]);
    } else {
        s = ((const int*)ei)[e];
        c = ((const int*)ei)[N_EDGES + e];
    }
    if ((unsigned)s >= N_NODES) s = 0;
    if ((unsigned)c >= N_NODES) c = 0;
    g_src[e] = s;
    g_dst[e] = c;
    atomicAdd(&g_deg[c], 1);
}

// scan pass 1: per-block exclusive scan of deg (edge count), fused dinv (deg+1 w/ self-loop)
__global__ void k_scan1() {
    __shared__ int wsum[32];
    int t = threadIdx.x;
    int i = blockIdx.x * SCAN_B + t;
    int lane = t & 31, wid = t >> 5;
    int v = 0;
    if (i < N_NODES) {
        int d = g_deg[i];
        v = d;
        g_dinv[i] = rsqrtf((float)(d + 1));
    }
    int x = v;
    #pragma unroll
    for (int d = 1; d < 32; d <<= 1) {
        int y = __shfl_up_sync(0xffffffffu, x, d);
        if (lane >= d) x += y;
    }
    if (lane == 31) wsum[wid] = x;
    __syncthreads();
    if (wid == 0) {
        int y = wsum[lane];
        #pragma unroll
        for (int d = 1; d < 32; d <<= 1) {
            int z = __shfl_up_sync(0xffffffffu, y, d);
            if (lane >= d) y += z;
        }
        wsum[lane] = y;
    }
    __syncthreads();
    int base = (wid > 0) ? wsum[wid - 1] : 0;
    if (i < N_NODES) g_rowptr[i] = base + x - v;
    if (t == SCAN_B - 1) g_bsum[blockIdx.x] = wsum[31];
}

// scan pass 2: each block sums its prefix of block sums, adds offset
__global__ void k_scan3() {
    __shared__ int s_part[2];
    __shared__ int s_off;
    int t = threadIdx.x;
    if (t < 64) {
        int v = (t < blockIdx.x) ? g_bsum[t] : 0;
        #pragma unroll
        for (int d = 16; d; d >>= 1) v += __shfl_down_sync(0xffffffffu, v, d);
        if ((t & 31) == 0) s_part[t >> 5] = v;
    }
    __syncthreads();
    if (t == 0) s_off = s_part[0] + s_part[1];
    __syncthreads();
    int i = blockIdx.x * SCAN_B + t;
    if (i < N_NODES) g_rowptr[i] += s_off;
    if (i == 0) g_rowptr[N_NODES] = N_EDGES;
}

__global__ void k_fill() {
    int e = blockIdx.x * blockDim.x + threadIdx.x;
    if (e < N_EDGES) {
        int c = g_dst[e];
        int pos = g_rowptr[c] + atomicAdd(&g_fill[c], 1);
        if ((unsigned)pos < N_EDGES) g_csr[pos] = g_src[e];
    }
}

// ---------------------------------------------------------------------------
// tf32 tensor-core GEMM: C[M,128] = A[M,128] @ B[128,128]
__device__ __forceinline__ unsigned f2tf32(float f) {
    unsigned u;
    asm("cvt.rna.tf32.f32 %0, %1;" : "=r"(u) : "f"(f));
    return u;
}

__device__ __forceinline__ void mma_tf32(float& c0, float& c1, float& c2, float& c3,
                                         unsigned a0, unsigned a1, unsigned a2, unsigned a3,
                                         unsigned b0, unsigned b1) {
    asm volatile(
        "mma.sync.aligned.m16n8k8.row.col.f32.tf32.tf32.f32 "
        "{%0,%1,%2,%3}, {%4,%5,%6,%7}, {%8,%9}, {%0,%1,%2,%3};"
        : "+f"(c0), "+f"(c1), "+f"(c2), "+f"(c3)
        : "r"(a0), "r"(a1), "r"(a2), "r"(a3), "r"(b0), "r"(b1));
}

__device__ __forceinline__ void gemm_tf32_body(const float* __restrict__ A,
                                               const float* __restrict__ B,
                                               float* __restrict__ C, int M) {
    extern __shared__ unsigned smem_u[];
    unsigned* Bs = smem_u;                    // [128][PAD_B]
    unsigned* As = smem_u + 128 * PAD_B;      // [128][PAD_A]
    int tid = threadIdx.x;                    // 256
    int lane = tid & 31, wid = tid >> 5;
    int g = lane >> 2, t4 = lane & 3;
    int wm = wid >> 1, wn = wid & 1;
    int m_base = wm * 32, n_base = wn * 64;
    int m0 = blockIdx.x * 128;

    for (int idx = tid; idx < 128 * 32; idx += 256) {
        int k = idx >> 5, nq = (idx & 31) << 2;
        float4 v = *(const float4*)(B + (size_t)k * 128 + nq);
        unsigned* d = &Bs[k * PAD_B + nq];
        d[0] = f2tf32(v.x); d[1] = f2tf32(v.y);
        d[2] = f2tf32(v.z); d[3] = f2tf32(v.w);
    }

    float acc[2][8][4];
    #pragma unroll
    for (int mi = 0; mi < 2; mi++)
        #pragma unroll
        for (int ni = 0; ni < 8; ni++)
            #pragma unroll
            for (int q = 0; q < 4; q++) acc[mi][ni][q] = 0.f;

    for (int kc = 0; kc < 4; kc++) {
        int k0c = kc * 32;
        __syncthreads();
        for (int idx = tid; idx < 128 * 8; idx += 256) {
            int m = idx >> 3, kq = (idx & 7) << 2;
            float4 v = make_float4(0.f, 0.f, 0.f, 0.f);
            if (m0 + m < M) v = *(const float4*)(A + (size_t)(m0 + m) * 128 + k0c + kq);
            unsigned* d = &As[m * PAD_A + kq];
            d[0] = f2tf32(v.x); d[1] = f2tf32(v.y);
            d[2] = f2tf32(v.z); d[3] = f2tf32(v.w);
        }
        __syncthreads();
        #pragma unroll
        for (int kk = 0; kk < 4; kk++) {
            int k0 = kk * 8;
            unsigned a[2][4];
            #pragma unroll
            for (int mi = 0; mi < 2; mi++) {
                int r0 = m_base + mi * 16 + g;
                a[mi][0] = As[r0 * PAD_A + k0 + t4];
                a[mi][1] = As[(r0 + 8) * PAD_A + k0 + t4];
                a[mi][2] = As[r0 * PAD_A + k0 + t4 + 4];
                a[mi][3] = As[(r0 + 8) * PAD_A + k0 + t4 + 4];
            }
            unsigned b[8][2];
            int K0 = k0c + k0;
            #pragma unroll
            for (int ni = 0; ni < 8; ni++) {
                int cbase = n_base + ni * 8 + g;
                b[ni][0] = Bs[(K0 + t4) * PAD_B + cbase];
                b[ni][1] = Bs[(K0 + t4 + 4) * PAD_B + cbase];
            }
            #pragma unroll
            for (int mi = 0; mi < 2; mi++)
                #pragma unroll
                for (int ni = 0; ni < 8; ni++)
                    mma_tf32(acc[mi][ni][0], acc[mi][ni][1], acc[mi][ni][2], acc[mi][ni][3],
                             a[mi][0], a[mi][1], a[mi][2], a[mi][3],
                             b[ni][0], b[ni][1]);
        }
    }

    #pragma unroll
    for (int mi = 0; mi < 2; mi++) {
        int r0 = m0 + m_base + mi * 16 + g;
        int r1 = r0 + 8;
        #pragma unroll
        for (int ni = 0; ni < 8; ni++) {
            int col = n_base + ni * 8 + 2 * t4;
            if (r0 < M)
                *(float2*)(C + (size_t)r0 * 128 + col) = make_float2(acc[mi][ni][0], acc[mi][ni][1]);
            if (r1 < M)
                *(float2*)(C + (size_t)r1 * 128 + col) = make_float2(acc[mi][ni][2], acc[mi][ni][3]);
        }
    }
}

__global__ void k_gemm1(const float* __restrict__ A, const float* __restrict__ B) {
    gemm_tf32_body(A, B, g_h1, N_NODES);
}
__global__ void k_gemm2() {
    gemm_tf32_body(g_hidden, g_wc, g_h23, N_NODES);
}

// ---------------------------------------------------------------------------
// warp-per-node gather, unroll-4 for MLP
__device__ __forceinline__ float4 gather_row(const float* __restrict__ h, int node,
                                             int lane) {
    int start = __ldg(&g_rowptr[node]);
    int end   = __ldg(&g_rowptr[node + 1]);
    float4 a0 = make_float4(0.f, 0.f, 0.f, 0.f);
    float4 a1 = make_float4(0.f, 0.f, 0.f, 0.f);
    float4 a2 = make_float4(0.f, 0.f, 0.f, 0.f);
    float4 a3 = make_float4(0.f, 0.f, 0.f, 0.f);
    int j = start;
    for (; j + 3 < end; j += 4) {
        int s0 = __ldg(&g_csr[j]);
        int s1 = __ldg(&g_csr[j + 1]);
        int s2 = __ldg(&g_csr[j + 2]);
        int s3 = __ldg(&g_csr[j + 3]);
        float w0 = __ldg(&g_dinv[s0]);
        float w1 = __ldg(&g_dinv[s1]);
        float w2 = __ldg(&g_dinv[s2]);
        float w3 = __ldg(&g_dinv[s3]);
        float4 v0 = *(const float4*)(h + (size_t)s0 * CH + lane * 4);
        float4 v1 = *(const float4*)(h + (size_t)s1 * CH + lane * 4);
        float4 v2 = *(const float4*)(h + (size_t)s2 * CH + lane * 4);
        float4 v3 = *(const float4*)(h + (size_t)s3 * CH + lane * 4);
        a0.x = fmaf(w0, v0.x, a0.x); a1.x = fmaf(w1, v1.x, a1.x);
        a0.y = fmaf(w0, v0.y, a0.y); a1.y = fmaf(w1, v1.y, a1.y);
        a0.z = fmaf(w0, v0.z, a0.z); a1.z = fmaf(w1, v1.z, a1.z);
        a0.w = fmaf(w0, v0.w, a0.w); a1.w = fmaf(w1, v1.w, a1.w);
        a2.x = fmaf(w2, v2.x, a2.x); a3.x = fmaf(w3, v3.x, a3.x);
        a2.y = fmaf(w2, v2.y, a2.y); a3.y = fmaf(w3, v3.y, a3.y);
        a2.z = fmaf(w2, v2.z, a2.z); a3.z = fmaf(w3, v3.z, a3.z);
        a2.w = fmaf(w2, v2.w, a2.w); a3.w = fmaf(w3, v3.w, a3.w);
    }
    for (; j < end; j++) {
        int s0 = __ldg(&g_csr[j]);
        float w0 = __ldg(&g_dinv[s0]);
        float4 v0 = *(const float4*)(h + (size_t)s0 * CH + lane * 4);
        a0.x = fmaf(w0, v0.x, a0.x);
        a0.y = fmaf(w0, v0.y, a0.y);
        a0.z = fmaf(w0, v0.z, a0.z);
        a0.w = fmaf(w0, v0.w, a0.w);
    }
    a0.x += a1.x + a2.x + a3.x;
    a0.y += a1.y + a2.y + a3.y;
    a0.z += a1.z + a2.z + a3.z;
    a0.w += a1.w + a2.w + a3.w;
    return a0;
}

__global__ void k_gather1(const float* __restrict__ b1) {
    int gtid = blockIdx.x * blockDim.x + threadIdx.x;
    int node = gtid >> 5;
    int lane = gtid & 31;
    if (node >= N_NODES) return;
    float4 acc = gather_row(g_h1, node, lane);
    float me = __ldg(&g_dinv[node]);
    float m2 = me * me;
    float4 self = *(const float4*)(g_h1 + (size_t)node * CH + lane * 4);
    float4 bb   = *(const float4*)(b1 + lane * 4);
    float4 o;
    o.x = fmaxf(fmaf(acc.x, me, fmaf(self.x, m2, bb.x)), 0.f);
    o.y = fmaxf(fmaf(acc.y, me, fmaf(self.y, m2, bb.y)), 0.f);
    o.z = fmaxf(fmaf(acc.z, me, fmaf(self.z, m2, bb.z)), 0.f);
    o.w = fmaxf(fmaf(acc.w, me, fmaf(self.w, m2, bb.w)), 0.f);
    *(float4*)(g_hidden + (size_t)node * CH + lane * 4) = o;
}

__global__ void k_gather2(const float* __restrict__ b2, const float* __restrict__ b3,
                          float* __restrict__ out) {
    int gtid = blockIdx.x * blockDim.x + threadIdx.x;
    int node = gtid >> 5;
    int lane = gtid & 31;
    if (node >= N_NODES) return;
    float4 acc = gather_row(g_h23, node, lane);
    float me = __ldg(&g_dinv[node]);
    float m2 = me * me;
    float4 self = *(const float4*)(g_h23 + (size_t)node * CH + lane * 4);
    const float* bias = (lane < 16) ? (b2 + lane * 4) : (b3 + (lane - 16) * 4);
    float4 bb = *(const float4*)bias;
    float4 o;
    o.x = fmaxf(fmaf(acc.x, me, fmaf(self.x, m2, bb.x)), 0.f);
    o.y = fmaxf(fmaf(acc.y, me, fmaf(self.y, m2, bb.y)), 0.f);
    o.z = fmaxf(fmaf(acc.z, me, fmaf(self.z, m2, bb.z)), 0.f);
    o.w = fmaxf(fmaf(acc.w, me, fmaf(self.w, m2, bb.w)), 0.f);
    float* dst = (lane < 16)
        ? (out + (size_t)node * OUT_CH + lane * 4)
        : (out + (size_t)N_NODES * OUT_CH + (size_t)node * OUT_CH + (lane - 16) * 4);
    *(float4*)dst = o;
}

// ---------------------------------------------------------------------------
extern "C" void kernel_launch(void* const* d_in, const int* in_sizes, int n_in,
                              void* d_out, int out_size) {
    const float* x  = (const float*)d_in[0];
    const void*  ei = d_in[1];
    const float* W1 = (const float*)d_in[2];
    const float* b1 = (const float*)d_in[3];
    const float* W2 = (const float*)d_in[4];
    const float* b2 = (const float*)d_in[5];
    const float* W3 = (const float*)d_in[6];
    const float* b3 = (const float*)d_in[7];
    float* out = (float*)d_out;

    cudaFuncSetAttribute(k_gemm1, cudaFuncAttributeMaxDynamicSharedMemorySize, GEMM_SMEM);
    cudaFuncSetAttribute(k_gemm2, cudaFuncAttributeMaxDynamicSharedMemorySize, GEMM_SMEM);

    k_pre<<<(N_NODES + 255) / 256, 256>>>(ei, W2, W3);
    k_deg<<<(N_EDGES + 255) / 256, 256>>>(ei);
    k_scan1<<<SCAN_NB, SCAN_B>>>();
    k_scan3<<<SCAN_NB, SCAN_B>>>();
    k_fill<<<(N_EDGES + 255) / 256, 256>>>();

    k_gemm1<<<(N_NODES + 127) / 128, 256, GEMM_SMEM>>>(x, W1);
    k_gather1<<<(N_NODES * 32 + 255) / 256, 256>>>(b1);

    k_gemm2<<<(N_NODES + 127) / 128, 256, GEMM_SMEM>>>();
    k_gather2<<<(N_NODES * 32 + 255) / 256, 256>>>(b2, b3, out);
}

// round 12
// speedup vs baseline: 1.1526x; 1.1526x over previous
#include <cuda_runtime.h>
#include <cuda_fp16.h>

#define N_NODES 50000
#define N_EDGES 800000
#define CH 128
#define OUT_CH 64
#define SCAN_B 1024
#define SCAN_NB ((N_NODES + SCAN_B - 1) / SCAN_B)   // 49
#define PAD_A 36
#define PAD_B 136
#define GEMM_SMEM ((128 * PAD_B + 128 * PAD_A) * 4)

// ---- persistent device scratch (no allocation allowed) ----
__device__ int   g_is64;
__device__ int   g_deg[N_NODES];
__device__ float g_dinv[N_NODES];
__device__ int   g_rowptr[N_NODES + 1];
__device__ int   g_fill[N_NODES];
__device__ int   g_bsum[64];
__device__ int   g_csr[N_EDGES];
__device__ __align__(16) __half g_h1h[(size_t)N_NODES * CH];
__device__ __align__(16) __half g_hidh[(size_t)N_NODES * CH];
__device__ __align__(16) __half g_h23h[(size_t)N_NODES * CH];
__device__ __align__(16) float  g_wc[CH * CH];

__device__ __forceinline__ int edge_at(const void* p, int i) {
    if (g_is64) return (int)(((const long long*)p)[i]);
    return ((const int*)p)[i];
}

// ---------------------------------------------------------------------------
__global__ void k_pre(const void* ei, const float* __restrict__ W2,
                      const float* __restrict__ W3) {
    int i = blockIdx.x * blockDim.x + threadIdx.x;
    if (i < N_NODES) { g_deg[i] = 1; g_fill[i] = 0; }
    if (i < CH * CH) {
        int k = i >> 7, c = i & 127;
        g_wc[i] = (c < OUT_CH) ? W2[k * OUT_CH + c] : W3[k * OUT_CH + (c - OUT_CH)];
    }
    if (i == 0) {
        const long long* p = (const long long*)ei;
        int ok64 = 1;
        for (int t = 0; t < 256; t++) {
            long long v = p[t];
            if (v < 0 || v >= N_NODES) { ok64 = 0; break; }
        }
        g_is64 = ok64;
    }
}

__global__ void k_deg(const void* __restrict__ ei) {
    int e = blockIdx.x * blockDim.x + threadIdx.x;
    if (e < N_EDGES) {
        int c = edge_at(ei, N_EDGES + e);
        if ((unsigned)c < N_NODES) atomicAdd(&g_deg[c], 1);
    }
}

// scan pass 1: per-block exclusive scan of (deg-1), fused dinv
__global__ void k_scan1() {
    __shared__ int wsum[32];
    int t = threadIdx.x;
    int i = blockIdx.x * SCAN_B + t;
    int lane = t & 31, wid = t >> 5;
    int v = 0;
    if (i < N_NODES) {
        int d = g_deg[i];
        v = d - 1;
        g_dinv[i] = rsqrtf((float)d);
    }
    int x = v;
    #pragma unroll
    for (int d = 1; d < 32; d <<= 1) {
        int y = __shfl_up_sync(0xffffffffu, x, d);
        if (lane >= d) x += y;
    }
    if (lane == 31) wsum[wid] = x;
    __syncthreads();
    if (wid == 0) {
        int y = wsum[lane];
        #pragma unroll
        for (int d = 1; d < 32; d <<= 1) {
            int z = __shfl_up_sync(0xffffffffu, y, d);
            if (lane >= d) y += z;
        }
        wsum[lane] = y;
    }
    __syncthreads();
    int base = (wid > 0) ? wsum[wid - 1] : 0;
    if (i < N_NODES) g_rowptr[i] = base + x - v;
    if (t == SCAN_B - 1) g_bsum[blockIdx.x] = wsum[31];
}

// scan pass 2: each block sums its prefix of block sums, adds offset
__global__ void k_scan3() {
    __shared__ int s_part[2];
    __shared__ int s_off;
    int t = threadIdx.x;
    if (t < 64) {
        int v = (t < blockIdx.x) ? g_bsum[t] : 0;
        #pragma unroll
        for (int d = 16; d; d >>= 1) v += __shfl_down_sync(0xffffffffu, v, d);
        if ((t & 31) == 0) s_part[t >> 5] = v;
    }
    __syncthreads();
    if (t == 0) s_off = s_part[0] + s_part[1];
    __syncthreads();
    int i = blockIdx.x * SCAN_B + t;
    if (i < N_NODES) g_rowptr[i] += s_off;
    if (i == 0) g_rowptr[N_NODES] = N_EDGES;
}

__global__ void k_fill(const void* __restrict__ ei) {
    int e = blockIdx.x * blockDim.x + threadIdx.x;
    if (e < N_EDGES) {
        int s = edge_at(ei, e);
        int c = edge_at(ei, N_EDGES + e);
        if ((unsigned)c < N_NODES && (unsigned)s < N_NODES) {
            int pos = g_rowptr[c] + atomicAdd(&g_fill[c], 1);
            if ((unsigned)pos < N_EDGES) g_csr[pos] = s;
        }
    }
}

// ---------------------------------------------------------------------------
// tf32 tensor-core GEMM: C_half[M,128] = A[M,128] @ B[128,128]
__device__ __forceinline__ unsigned f2tf32(float f) {
    unsigned u;
    asm("cvt.rna.tf32.f32 %0, %1;" : "=r"(u) : "f"(f));
    return u;
}

__device__ __forceinline__ void mma_tf32(float& c0, float& c1, float& c2, float& c3,
                                         unsigned a0, unsigned a1, unsigned a2, unsigned a3,
                                         unsigned b0, unsigned b1) {
    asm volatile(
        "mma.sync.aligned.m16n8k8.row.col.f32.tf32.tf32.f32 "
        "{%0,%1,%2,%3}, {%4,%5,%6,%7}, {%8,%9}, {%0,%1,%2,%3};"
        : "+f"(c0), "+f"(c1), "+f"(c2), "+f"(c3)
        : "r"(a0), "r"(a1), "r"(a2), "r"(a3), "r"(b0), "r"(b1));
}

template <bool A_HALF>
__device__ __forceinline__ void gemm_tf32_body(const void* __restrict__ Av,
                                               const float* __restrict__ B,
                                               __half* __restrict__ C, int M) {
    extern __shared__ unsigned smem_u[];
    unsigned* Bs = smem_u;                    // [128][PAD_B]
    unsigned* As = smem_u + 128 * PAD_B;      // [128][PAD_A]
    int tid = threadIdx.x;                    // 256
    int lane = tid & 31, wid = tid >> 5;
    int g = lane >> 2, t4 = lane & 3;
    int wm = wid >> 1, wn = wid & 1;
    int m_base = wm * 32, n_base = wn * 64;
    int m0 = blockIdx.x * 128;

    for (int idx = tid; idx < 128 * 32; idx += 256) {
        int k = idx >> 5, nq = (idx & 31) << 2;
        float4 v = *(const float4*)(B + (size_t)k * 128 + nq);
        unsigned* d = &Bs[k * PAD_B + nq];
        d[0] = f2tf32(v.x); d[1] = f2tf32(v.y);
        d[2] = f2tf32(v.z); d[3] = f2tf32(v.w);
    }

    float acc[2][8][4];
    #pragma unroll
    for (int mi = 0; mi < 2; mi++)
        #pragma unroll
        for (int ni = 0; ni < 8; ni++)
            #pragma unroll
            for (int q = 0; q < 4; q++) acc[mi][ni][q] = 0.f;

    for (int kc = 0; kc < 4; kc++) {
        int k0c = kc * 32;
        __syncthreads();
        for (int idx = tid; idx < 128 * 8; idx += 256) {
            int m = idx >> 3, kq = (idx & 7) << 2;
            float4 v = make_float4(0.f, 0.f, 0.f, 0.f);
            if (m0 + m < M) {
                if (A_HALF) {
                    const __half2* p = (const __half2*)((const __half*)Av +
                                        (size_t)(m0 + m) * 128 + k0c + kq);
                    float2 f01 = __half22float2(p[0]);
                    float2 f23 = __half22float2(p[1]);
                    v = make_float4(f01.x, f01.y, f23.x, f23.y);
                } else {
                    v = *(const float4*)((const float*)Av + (size_t)(m0 + m) * 128 + k0c + kq);
                }
            }
            unsigned* d = &As[m * PAD_A + kq];
            d[0] = f2tf32(v.x); d[1] = f2tf32(v.y);
            d[2] = f2tf32(v.z); d[3] = f2tf32(v.w);
        }
        __syncthreads();
        #pragma unroll
        for (int kk = 0; kk < 4; kk++) {
            int k0 = kk * 8;
            unsigned a[2][4];
            #pragma unroll
            for (int mi = 0; mi < 2; mi++) {
                int r0 = m_base + mi * 16 + g;
                a[mi][0] = As[r0 * PAD_A + k0 + t4];
                a[mi][1] = As[(r0 + 8) * PAD_A + k0 + t4];
                a[mi][2] = As[r0 * PAD_A + k0 + t4 + 4];
                a[mi][3] = As[(r0 + 8) * PAD_A + k0 + t4 + 4];
            }
            unsigned b[8][2];
            int K0 = k0c + k0;
            #pragma unroll
            for (int ni = 0; ni < 8; ni++) {
                int cbase = n_base + ni * 8 + g;
                b[ni][0] = Bs[(K0 + t4) * PAD_B + cbase];
                b[ni][1] = Bs[(K0 + t4 + 4) * PAD_B + cbase];
            }
            #pragma unroll
            for (int mi = 0; mi < 2; mi++)
                #pragma unroll
                for (int ni = 0; ni < 8; ni++)
                    mma_tf32(acc[mi][ni][0], acc[mi][ni][1], acc[mi][ni][2], acc[mi][ni][3],
                             a[mi][0], a[mi][1], a[mi][2], a[mi][3],
                             b[ni][0], b[ni][1]);
        }
    }

    #pragma unroll
    for (int mi = 0; mi < 2; mi++) {
        int r0 = m0 + m_base + mi * 16 + g;
        int r1 = r0 + 8;
        #pragma unroll
        for (int ni = 0; ni < 8; ni++) {
            int col = n_base + ni * 8 + 2 * t4;
            if (r0 < M)
                *(__half2*)(C + (size_t)r0 * 128 + col) =
                    __floats2half2_rn(acc[mi][ni][0], acc[mi][ni][1]);
            if (r1 < M)
                *(__half2*)(C + (size_t)r1 * 128 + col) =
                    __floats2half2_rn(acc[mi][ni][2], acc[mi][ni][3]);
        }
    }
}

__global__ void k_gemm1(const float* __restrict__ A, const float* __restrict__ B) {
    gemm_tf32_body<false>(A, B, g_h1h, N_NODES);
}
__global__ void k_gemm2() {
    gemm_tf32_body<true>(g_hidh, g_wc, g_h23h, N_NODES);
}

// ---------------------------------------------------------------------------
// warp-per-node gather over fp16 rows, fp32 accumulate, unroll-2
__device__ __forceinline__ float4 gather_row_h(const __half* __restrict__ h, int node,
                                               int lane) {
    int start = __ldg(&g_rowptr[node]);
    int end   = __ldg(&g_rowptr[node + 1]);
    float4 a0 = make_float4(0.f, 0.f, 0.f, 0.f);
    float4 a1 = make_float4(0.f, 0.f, 0.f, 0.f);
    int j = start;
    for (; j + 1 < end; j += 2) {
        int s0 = __ldg(&g_csr[j]);
        int s1 = __ldg(&g_csr[j + 1]);
        float w0 = __ldg(&g_dinv[s0]);
        float w1 = __ldg(&g_dinv[s1]);
        const __half2* p0 = (const __half2*)(h + (size_t)s0 * CH) + lane * 2;
        const __half2* p1 = (const __half2*)(h + (size_t)s1 * CH) + lane * 2;
        float2 u0 = __half22float2(p0[0]);
        float2 u1 = __half22float2(p0[1]);
        float2 v0 = __half22float2(p1[0]);
        float2 v1 = __half22float2(p1[1]);
        a0.x = fmaf(w0, u0.x, a0.x); a1.x = fmaf(w1, v0.x, a1.x);
        a0.y = fmaf(w0, u0.y, a0.y); a1.y = fmaf(w1, v0.y, a1.y);
        a0.z = fmaf(w0, u1.x, a0.z); a1.z = fmaf(w1, v1.x, a1.z);
        a0.w = fmaf(w0, u1.y, a0.w); a1.w = fmaf(w1, v1.y, a1.w);
    }
    if (j < end) {
        int s0 = __ldg(&g_csr[j]);
        float w0 = __ldg(&g_dinv[s0]);
        const __half2* p0 = (const __half2*)(h + (size_t)s0 * CH) + lane * 2;
        float2 u0 = __half22float2(p0[0]);
        float2 u1 = __half22float2(p0[1]);
        a0.x = fmaf(w0, u0.x, a0.x);
        a0.y = fmaf(w0, u0.y, a0.y);
        a0.z = fmaf(w0, u1.x, a0.z);
        a0.w = fmaf(w0, u1.y, a0.w);
    }
    a0.x += a1.x; a0.y += a1.y; a0.z += a1.z; a0.w += a1.w;
    return a0;
}

__global__ void k_gather1(const float* __restrict__ b1) {
    int gtid = blockIdx.x * blockDim.x + threadIdx.x;
    int node = gtid >> 5;
    int lane = gtid & 31;
    if (node >= N_NODES) return;
    float4 acc = gather_row_h(g_h1h, node, lane);
    float me = __ldg(&g_dinv[node]);
    float m2 = me * me;
    const __half2* sp = (const __half2*)(g_h1h + (size_t)node * CH) + lane * 2;
    float2 s01 = __half22float2(sp[0]);
    float2 s23 = __half22float2(sp[1]);
    float4 bb = *(const float4*)(b1 + lane * 4);
    float ox = fmaxf(fmaf(acc.x, me, fmaf(s01.x, m2, bb.x)), 0.f);
    float oy = fmaxf(fmaf(acc.y, me, fmaf(s01.y, m2, bb.y)), 0.f);
    float oz = fmaxf(fmaf(acc.z, me, fmaf(s23.x, m2, bb.z)), 0.f);
    float ow = fmaxf(fmaf(acc.w, me, fmaf(s23.y, m2, bb.w)), 0.f);
    __half2* dp = (__half2*)(g_hidh + (size_t)node * CH) + lane * 2;
    dp[0] = __floats2half2_rn(ox, oy);
    dp[1] = __floats2half2_rn(oz, ow);
}

__global__ void k_gather2(const float* __restrict__ b2, const float* __restrict__ b3,
                          float* __restrict__ out) {
    int gtid = blockIdx.x * blockDim.x + threadIdx.x;
    int node = gtid >> 5;
    int lane = gtid & 31;
    if (node >= N_NODES) return;
    float4 acc = gather_row_h(g_h23h, node, lane);
    float me = __ldg(&g_dinv[node]);
    float m2 = me * me;
    const __half2* sp = (const __half2*)(g_h23h + (size_t)node * CH) + lane * 2;
    float2 s01 = __half22float2(sp[0]);
    float2 s23 = __half22float2(sp[1]);
    const float* bias = (lane < 16) ? (b2 + lane * 4) : (b3 + (lane - 16) * 4);
    float4 bb = *(const float4*)bias;
    float4 o;
    o.x = fmaxf(fmaf(acc.x, me, fmaf(s01.x, m2, bb.x)), 0.f);
    o.y = fmaxf(fmaf(acc.y, me, fmaf(s01.y, m2, bb.y)), 0.f);
    o.z = fmaxf(fmaf(acc.z, me, fmaf(s23.x, m2, bb.z)), 0.f);
    o.w = fmaxf(fmaf(acc.w, me, fmaf(s23.y, m2, bb.w)), 0.f);
    float* dst = (lane < 16)
        ? (out + (size_t)node * OUT_CH + lane * 4)
        : (out + (size_t)N_NODES * OUT_CH + (size_t)node * OUT_CH + (lane - 16) * 4);
    *(float4*)dst = o;
}

// ---------------------------------------------------------------------------
extern "C" void kernel_launch(void* const* d_in, const int* in_sizes, int n_in,
                              void* d_out, int out_size) {
    const float* x  = (const float*)d_in[0];
    const void*  ei = d_in[1];
    const float* W1 = (const float*)d_in[2];
    const float* b1 = (const float*)d_in[3];
    const float* W2 = (const float*)d_in[4];
    const float* b2 = (const float*)d_in[5];
    const float* W3 = (const float*)d_in[6];
    const float* b3 = (const float*)d_in[7];
    float* out = (float*)d_out;

    cudaFuncSetAttribute(k_gemm1, cudaFuncAttributeMaxDynamicSharedMemorySize, GEMM_SMEM);
    cudaFuncSetAttribute(k_gemm2, cudaFuncAttributeMaxDynamicSharedMemorySize, GEMM_SMEM);

    k_pre<<<(N_NODES + 255) / 256, 256>>>(ei, W2, W3);
    k_deg<<<(N_EDGES + 255) / 256, 256>>>(ei);
    k_scan1<<<SCAN_NB, SCAN_B>>>();
    k_scan3<<<SCAN_NB, SCAN_B>>>();
    k_fill<<<(N_EDGES + 255) / 256, 256>>>(ei);

    k_gemm1<<<(N_NODES + 127) / 128, 256, GEMM_SMEM>>>(x, W1);
    k_gather1<<<(N_NODES * 32 + 255) / 256, 256>>>(b1);

    k_gemm2<<<(N_NODES + 127) / 128, 256, GEMM_SMEM>>>();
    k_gather2<<<(N_NODES * 32 + 255) / 256, 256>>>(b2, b3, out);
}

// round 15
// speedup vs baseline: 1.1808x; 1.0244x over previous
#include <cuda_runtime.h>
#include <cuda_fp16.h>

#define N_NODES 50000
#define N_EDGES 800000
#define CH 128
#define OUT_CH 64
#define SCAN_B 1024
#define SCAN_NB ((N_NODES + SCAN_B - 1) / SCAN_B)   // 49
#define PAD_A 36
#define PAD_B 136
#define GEMM_SMEM ((128 * PAD_B + 128 * PAD_A) * 4)

// ---- persistent device scratch (no allocation allowed) ----
__device__ int   g_is64;
__device__ int   g_deg[N_NODES];
__device__ float g_dinv[N_NODES];
__device__ int   g_rowptr[N_NODES + 1];
__device__ int   g_fill[N_NODES];
__device__ int   g_bsum[64];
__device__ int   g_scan_ctr;
__device__ int   g_csr[N_EDGES];
__device__ __align__(16) __half g_h1h[(size_t)N_NODES * CH];
__device__ __align__(16) __half g_hidh[(size_t)N_NODES * CH];
__device__ __align__(16) __half g_h23h[(size_t)N_NODES * CH];
__device__ __align__(16) float  g_wc[CH * CH];

__device__ __forceinline__ int edge_at(const void* p, int i) {
    if (g_is64) return (int)(((const long long*)p)[i]);
    return ((const int*)p)[i];
}

// ---------------------------------------------------------------------------
__global__ void k_pre(const void* ei, const float* __restrict__ W2,
                      const float* __restrict__ W3) {
    int i = blockIdx.x * blockDim.x + threadIdx.x;
    if (i < N_NODES) { g_deg[i] = 1; g_fill[i] = 0; }
    if (i < CH * CH) {
        int k = i >> 7, c = i & 127;
        g_wc[i] = (c < OUT_CH) ? W2[k * OUT_CH + c] : W3[k * OUT_CH + (c - OUT_CH)];
    }
    if (i == 1) g_scan_ctr = 0;
    if (i == 0) {
        const long long* p = (const long long*)ei;
        int ok64 = 1;
        for (int t = 0; t < 256; t++) {
            long long v = p[t];
            if (v < 0 || v >= N_NODES) { ok64 = 0; break; }
        }
        g_is64 = ok64;
    }
}

__global__ void k_deg(const void* __restrict__ ei) {
    int e = blockIdx.x * blockDim.x + threadIdx.x;
    if (e < N_EDGES) {
        int c = edge_at(ei, N_EDGES + e);
        if ((unsigned)c < N_NODES) atomicAdd(&g_deg[c], 1);
    }
}

// fused scan: per-block scan of (deg-1) + dinv, grid-sync via atomic counter
// (49 blocks, all resident simultaneously -> spin is safe), then add prefix
// of block sums. rowptr complete at kernel exit.
__global__ void k_scan() {
    __shared__ int wsum[32];
    __shared__ int s_part[2];
    __shared__ int s_off;
    int t = threadIdx.x;
    int i = blockIdx.x * SCAN_B + t;
    int lane = t & 31, wid = t >> 5;
    int v = 0;
    if (i < N_NODES) {
        int d = g_deg[i];
        v = d - 1;
        g_dinv[i] = rsqrtf((float)d);
    }
    int x = v;
    #pragma unroll
    for (int d = 1; d < 32; d <<= 1) {
        int y = __shfl_up_sync(0xffffffffu, x, d);
        if (lane >= d) x += y;
    }
    if (lane == 31) wsum[wid] = x;
    __syncthreads();
    if (wid == 0) {
        int y = wsum[lane];
        #pragma unroll
        for (int d = 1; d < 32; d <<= 1) {
            int z = __shfl_up_sync(0xffffffffu, y, d);
            if (lane >= d) y += z;
        }
        wsum[lane] = y;
    }
    __syncthreads();
    int base = (wid > 0) ? wsum[wid - 1] : 0;
    int local = base + x - v;                 // block-local exclusive
    // publish block sum, grid sync
    if (t == 0) {
        g_bsum[blockIdx.x] = wsum[31];
        __threadfence();
        atomicAdd(&g_scan_ctr, 1);
    }
    if (t == 0) {
        while (atomicAdd(&g_scan_ctr, 0) < SCAN_NB) { }
    }
    __syncthreads();
    // sum of bsum[0..blockIdx.x)
    if (t < 64) {
        int w = (t < blockIdx.x) ? g_bsum[t] : 0;
        #pragma unroll
        for (int d = 16; d; d >>= 1) w += __shfl_down_sync(0xffffffffu, w, d);
        if ((t & 31) == 0) s_part[t >> 5] = w;
    }
    __syncthreads();
    if (t == 0) s_off = s_part[0] + s_part[1];
    __syncthreads();
    if (i < N_NODES) g_rowptr[i] = local + s_off;
    if (i == 0) g_rowptr[N_NODES] = N_EDGES;
}

__global__ void k_fill(const void* __restrict__ ei) {
    int e = blockIdx.x * blockDim.x + threadIdx.x;
    if (e < N_EDGES) {
        int s = edge_at(ei, e);
        int c = edge_at(ei, N_EDGES + e);
        if ((unsigned)c < N_NODES && (unsigned)s < N_NODES) {
            int pos = g_rowptr[c] + atomicAdd(&g_fill[c], 1);
            if ((unsigned)pos < N_EDGES) g_csr[pos] = s;
        }
    }
}

// ---------------------------------------------------------------------------
// tf32 tensor-core GEMM: C_half[M,128] = A[M,128] @ B[128,128]
__device__ __forceinline__ unsigned f2tf32(float f) {
    unsigned u;
    asm("cvt.rna.tf32.f32 %0, %1;" : "=r"(u) : "f"(f));
    return u;
}

__device__ __forceinline__ void mma_tf32(float& c0, float& c1, float& c2, float& c3,
                                         unsigned a0, unsigned a1, unsigned a2, unsigned a3,
                                         unsigned b0, unsigned b1) {
    asm volatile(
        "mma.sync.aligned.m16n8k8.row.col.f32.tf32.tf32.f32 "
        "{%0,%1,%2,%3}, {%4,%5,%6,%7}, {%8,%9}, {%0,%1,%2,%3};"
        : "+f"(c0), "+f"(c1), "+f"(c2), "+f"(c3)
        : "r"(a0), "r"(a1), "r"(a2), "r"(a3), "r"(b0), "r"(b1));
}

template <bool A_HALF>
__device__ __forceinline__ void gemm_tf32_body(const void* __restrict__ Av,
                                               const float* __restrict__ B,
                                               __half* __restrict__ C, int M) {
    extern __shared__ unsigned smem_u[];
    unsigned* Bs = smem_u;                    // [128][PAD_B]
    unsigned* As = smem_u + 128 * PAD_B;      // [128][PAD_A]
    int tid = threadIdx.x;                    // 256
    int lane = tid & 31, wid = tid >> 5;
    int g = lane >> 2, t4 = lane & 3;
    int wm = wid >> 1, wn = wid & 1;
    int m_base = wm * 32, n_base = wn * 64;
    int m0 = blockIdx.x * 128;

    for (int idx = tid; idx < 128 * 32; idx += 256) {
        int k = idx >> 5, nq = (idx & 31) << 2;
        float4 v = *(const float4*)(B + (size_t)k * 128 + nq);
        unsigned* d = &Bs[k * PAD_B + nq];
        d[0] = f2tf32(v.x); d[1] = f2tf32(v.y);
        d[2] = f2tf32(v.z); d[3] = f2tf32(v.w);
    }

    float acc[2][8][4];
    #pragma unroll
    for (int mi = 0; mi < 2; mi++)
        #pragma unroll
        for (int ni = 0; ni < 8; ni++)
            #pragma unroll
            for (int q = 0; q < 4; q++) acc[mi][ni][q] = 0.f;

    for (int kc = 0; kc < 4; kc++) {
        int k0c = kc * 32;
        __syncthreads();
        for (int idx = tid; idx < 128 * 8; idx += 256) {
            int m = idx >> 3, kq = (idx & 7) << 2;
            float4 v = make_float4(0.f, 0.f, 0.f, 0.f);
            if (m0 + m < M) {
                if (A_HALF) {
                    const __half2* p = (const __half2*)((const __half*)Av +
                                        (size_t)(m0 + m) * 128 + k0c + kq);
                    float2 f01 = __half22float2(p[0]);
                    float2 f23 = __half22float2(p[1]);
                    v = make_float4(f01.x, f01.y, f23.x, f23.y);
                } else {
                    v = *(const float4*)((const float*)Av + (size_t)(m0 + m) * 128 + k0c + kq);
                }
            }
            unsigned* d = &As[m * PAD_A + kq];
            d[0] = f2tf32(v.x); d[1] = f2tf32(v.y);
            d[2] = f2tf32(v.z); d[3] = f2tf32(v.w);
        }
        __syncthreads();
        #pragma unroll
        for (int kk = 0; kk < 4; kk++) {
            int k0 = kk * 8;
            unsigned a[2][4];
            #pragma unroll
            for (int mi = 0; mi < 2; mi++) {
                int r0 = m_base + mi * 16 + g;
                a[mi][0] = As[r0 * PAD_A + k0 + t4];
                a[mi][1] = As[(r0 + 8) * PAD_A + k0 + t4];
                a[mi][2] = As[r0 * PAD_A + k0 + t4 + 4];
                a[mi][3] = As[(r0 + 8) * PAD_A + k0 + t4 + 4];
            }
            unsigned b[8][2];
            int K0 = k0c + k0;
            #pragma unroll
            for (int ni = 0; ni < 8; ni++) {
                int cbase = n_base + ni * 8 + g;
                b[ni][0] = Bs[(K0 + t4) * PAD_B + cbase];
                b[ni][1] = Bs[(K0 + t4 + 4) * PAD_B + cbase];
            }
            #pragma unroll
            for (int mi = 0; mi < 2; mi++)
                #pragma unroll
                for (int ni = 0; ni < 8; ni++)
                    mma_tf32(acc[mi][ni][0], acc[mi][ni][1], acc[mi][ni][2], acc[mi][ni][3],
                             a[mi][0], a[mi][1], a[mi][2], a[mi][3],
                             b[ni][0], b[ni][1]);
        }
    }

    #pragma unroll
    for (int mi = 0; mi < 2; mi++) {
        int r0 = m0 + m_base + mi * 16 + g;
        int r1 = r0 + 8;
        #pragma unroll
        for (int ni = 0; ni < 8; ni++) {
            int col = n_base + ni * 8 + 2 * t4;
            if (r0 < M)
                *(__half2*)(C + (size_t)r0 * 128 + col) =
                    __floats2half2_rn(acc[mi][ni][0], acc[mi][ni][1]);
            if (r1 < M)
                *(__half2*)(C + (size_t)r1 * 128 + col) =
                    __floats2half2_rn(acc[mi][ni][2], acc[mi][ni][3]);
        }
    }
}

__global__ void k_gemm1(const float* __restrict__ A, const float* __restrict__ B) {
    gemm_tf32_body<false>(A, B, g_h1h, N_NODES);
}
__global__ void k_gemm2() {
    gemm_tf32_body<true>(g_hidh, g_wc, g_h23h, N_NODES);
}

// ---------------------------------------------------------------------------
// warp-per-node gather over fp16 rows: single 8B load per neighbor per lane
__device__ __forceinline__ float4 gather_row_h(const __half* __restrict__ h, int node,
                                               int lane) {
    int start = __ldg(&g_rowptr[node]);
    int end   = __ldg(&g_rowptr[node + 1]);
    float4 a0 = make_float4(0.f, 0.f, 0.f, 0.f);
    float4 a1 = make_float4(0.f, 0.f, 0.f, 0.f);
    int j = start;
    for (; j + 1 < end; j += 2) {
        int s0 = __ldg(&g_csr[j]);
        int s1 = __ldg(&g_csr[j + 1]);
        float w0 = __ldg(&g_dinv[s0]);
        float w1 = __ldg(&g_dinv[s1]);
        uint2 r0 = __ldg((const uint2*)(h + (size_t)s0 * CH) + lane);
        uint2 r1 = __ldg((const uint2*)(h + (size_t)s1 * CH) + lane);
        float2 u0 = __half22float2(*(__half2*)&r0.x);
        float2 u1 = __half22float2(*(__half2*)&r0.y);
        float2 v0 = __half22float2(*(__half2*)&r1.x);
        float2 v1 = __half22float2(*(__half2*)&r1.y);
        a0.x = fmaf(w0, u0.x, a0.x); a1.x = fmaf(w1, v0.x, a1.x);
        a0.y = fmaf(w0, u0.y, a0.y); a1.y = fmaf(w1, v0.y, a1.y);
        a0.z = fmaf(w0, u1.x, a0.z); a1.z = fmaf(w1, v1.x, a1.z);
        a0.w = fmaf(w0, u1.y, a0.w); a1.w = fmaf(w1, v1.y, a1.w);
    }
    if (j < end) {
        int s0 = __ldg(&g_csr[j]);
        float w0 = __ldg(&g_dinv[s0]);
        uint2 r0 = __ldg((const uint2*)(h + (size_t)s0 * CH) + lane);
        float2 u0 = __half22float2(*(__half2*)&r0.x);
        float2 u1 = __half22float2(*(__half2*)&r0.y);
        a0.x = fmaf(w0, u0.x, a0.x);
        a0.y = fmaf(w0, u0.y, a0.y);
        a0.z = fmaf(w0, u1.x, a0.z);
        a0.w = fmaf(w0, u1.y, a0.w);
    }
    a0.x += a1.x; a0.y += a1.y; a0.z += a1.z; a0.w += a1.w;
    return a0;
}

__global__ void k_gather1(const float* __restrict__ b1) {
    int gtid = blockIdx.x * blockDim.x + threadIdx.x;
    int node = gtid >> 5;
    int lane = gtid & 31;
    if (node >= N_NODES) return;
    float4 acc = gather_row_h(g_h1h, node, lane);
    float me = __ldg(&g_dinv[node]);
    float m2 = me * me;
    uint2 sr = __ldg((const uint2*)(g_h1h + (size_t)node * CH) + lane);
    float2 s01 = __half22float2(*(__half2*)&sr.x);
    float2 s23 = __half22float2(*(__half2*)&sr.y);
    float4 bb = *(const float4*)(b1 + lane * 4);
    float ox = fmaxf(fmaf(acc.x, me, fmaf(s01.x, m2, bb.x)), 0.f);
    float oy = fmaxf(fmaf(acc.y, me, fmaf(s01.y, m2, bb.y)), 0.f);
    float oz = fmaxf(fmaf(acc.z, me, fmaf(s23.x, m2, bb.z)), 0.f);
    float ow = fmaxf(fmaf(acc.w, me, fmaf(s23.y, m2, bb.w)), 0.f);
    __half2* dp = (__half2*)(g_hidh + (size_t)node * CH) + lane * 2;
    dp[0] = __floats2half2_rn(ox, oy);
    dp[1] = __floats2half2_rn(oz, ow);
}

__global__ void k_gather2(const float* __restrict__ b2, const float* __restrict__ b3,
                          float* __restrict__ out) {
    int gtid = blockIdx.x * blockDim.x + threadIdx.x;
    int node = gtid >> 5;
    int lane = gtid & 31;
    if (node >= N_NODES) return;
    float4 acc = gather_row_h(g_h23h, node, lane);
    float me = __ldg(&g_dinv[node]);
    float m2 = me * me;
    uint2 sr = __ldg((const uint2*)(g_h23h + (size_t)node * CH) + lane);
    float2 s01 = __half22float2(*(__half2*)&sr.x);
    float2 s23 = __half22float2(*(__half2*)&sr.y);
    const float* bias = (lane < 16) ? (b2 + lane * 4) : (b3 + (lane - 16) * 4);
    float4 bb = *(const float4*)bias;
    float4 o;
    o.x = fmaxf(fmaf(acc.x, me, fmaf(s01.x, m2, bb.x)), 0.f);
    o.y = fmaxf(fmaf(acc.y, me, fmaf(s01.y, m2, bb.y)), 0.f);
    o.z = fmaxf(fmaf(acc.z, me, fmaf(s23.x, m2, bb.z)), 0.f);
    o.w = fmaxf(fmaf(acc.w, me, fmaf(s23.y, m2, bb.w)), 0.f);
    float* dst = (lane < 16)
        ? (out + (size_t)node * OUT_CH + lane * 4)
        : (out + (size_t)N_NODES * OUT_CH + (size_t)node * OUT_CH + (lane - 16) * 4);
    *(float4*)dst = o;
}

// ---------------------------------------------------------------------------
extern "C" void kernel_launch(void* const* d_in, const int* in_sizes, int n_in,
                              void* d_out, int out_size) {
    const float* x  = (const float*)d_in[0];
    const void*  ei = d_in[1];
    const float* W1 = (const float*)d_in[2];
    const float* b1 = (const float*)d_in[3];
    const float* W2 = (const float*)d_in[4];
    const float* b2 = (const float*)d_in[5];
    const float* W3 = (const float*)d_in[6];
    const float* b3 = (const float*)d_in[7];
    float* out = (float*)d_out;

    cudaFuncSetAttribute(k_gemm1, cudaFuncAttributeMaxDynamicSharedMemorySize, GEMM_SMEM);
    cudaFuncSetAttribute(k_gemm2, cudaFuncAttributeMaxDynamicSharedMemorySize, GEMM_SMEM);

    k_pre<<<(N_NODES + 255) / 256, 256>>>(ei, W2, W3);
    k_deg<<<(N_EDGES + 255) / 256, 256>>>(ei);
    k_scan<<<SCAN_NB, SCAN_B>>>();
    k_fill<<<(N_EDGES + 255) / 256, 256>>>(ei);

    k_gemm1<<<(N_NODES + 127) / 128, 256, GEMM_SMEM>>>(x, W1);
    k_gather1<<<(N_NODES * 32 + 255) / 256, 256>>>(b1);

    k_gemm2<<<(N_NODES + 127) / 128, 256, GEMM_SMEM>>>();
    k_gather2<<<(N_NODES * 32 + 255) / 256, 256>>>(b2, b3, out);
}